// round 1
// baseline (speedup 1.0000x reference)
#include <cuda_runtime.h>
#include <math.h>

#define Bb   128
#define Pp   168
#define Mtot 8
#define HIDC 50
#define HIDR 50
#define HIDS 5
#define CKc  6
#define SKIP 24
#define HWw  24
#define PTt  6            // (P-CK)/SKIP
#define Ll   163          // P-CK+1
#define KDIM 1344         // P*M1*M2*M3
#define ODIM 50400        // P*HIDC*CK

// ---- scratch (device globals; no allocation allowed) ----
__device__ float g_c[Bb * ODIM];              // conv output [b][o]  (25.8 MB)
__device__ float g_res1T[Ll * Bb * HIDC];     // [t][b][h]
__device__ float g_h1[Bb * HIDR];
__device__ float g_hs[Bb * SKIP * HIDS];      // [b*24+j][u]

// ---- packed f32x2 helpers (sm_103a) ----
typedef unsigned long long ull;
__device__ __forceinline__ ull pack2(float lo, float hi) {
    ull r; asm("mov.b64 %0,{%1,%2};" : "=l"(r) : "f"(lo), "f"(hi)); return r;
}
__device__ __forceinline__ void fma2(ull& d, ull a, ull b) {
    asm("fma.rn.f32x2 %0,%1,%2,%3;" : "=l"(d) : "l"(a), "l"(b), "l"(d));
}
__device__ __forceinline__ void unpack2(ull v, float& lo, float& hi) {
    asm("mov.b64 {%0,%1},%2;" : "=f"(lo), "=f"(hi) : "l"(v));
}

__device__ __forceinline__ float sigm(float v) { return 1.f / (1.f + __expf(-v)); }
__device__ __forceinline__ float tanh_fast(float v) { return 2.f / (1.f + __expf(-2.f * v)) - 1.f; }

// ============================================================
// Kernel 1: conv GEMM  C[b][o] = relu(xf[b]·wf[o] + bias[o])
//   BM=128 (full batch), BN=128, BK=16, 256 thr, 8x8 micro-tile, f32x2 FMA
// ============================================================
__global__ __launch_bounds__(256) void conv_gemm_kernel(
    const float* __restrict__ x, const float* __restrict__ w,
    const float* __restrict__ bias)
{
    __shared__ float As[16][132];
    __shared__ float Bs[16][132];

    const int tid = threadIdx.x;
    const int n0  = blockIdx.x * 128;
    const int ty  = tid >> 4, tx = tid & 15;

    // load mapping: 2 float4 per tile per thread
    const int id0 = tid, id1 = tid + 256;
    const int ar0 = id0 >> 2, ac0 = (id0 & 3) * 4;
    const int ar1 = id1 >> 2, ac1 = (id1 & 3) * 4;

    const float* aptr0 = x + ar0 * KDIM + ac0;
    const float* aptr1 = x + ar1 * KDIM + ac1;
    const int o0 = n0 + ar0, o1 = n0 + ar1;
    const bool v0 = (o0 < ODIM), v1 = (o1 < ODIM);
    const float* bptr0 = w + (v0 ? o0 : 0) * KDIM + ac0;
    const float* bptr1 = w + (v1 ? o1 : 0) * KDIM + ac1;

    ull acc[8][4];
#pragma unroll
    for (int i = 0; i < 8; i++)
#pragma unroll
        for (int j = 0; j < 4; j++) acc[i][j] = 0ull;

    const float4 z4 = make_float4(0.f, 0.f, 0.f, 0.f);
    float4 a0 = *(const float4*)(aptr0);
    float4 a1 = *(const float4*)(aptr1);
    float4 b0 = v0 ? *(const float4*)(bptr0) : z4;
    float4 b1 = v1 ? *(const float4*)(bptr1) : z4;

    // store tile 0 (transposed)
    As[ac0+0][ar0]=a0.x; As[ac0+1][ar0]=a0.y; As[ac0+2][ar0]=a0.z; As[ac0+3][ar0]=a0.w;
    As[ac1+0][ar1]=a1.x; As[ac1+1][ar1]=a1.y; As[ac1+2][ar1]=a1.z; As[ac1+3][ar1]=a1.w;
    Bs[ac0+0][ar0]=b0.x; Bs[ac0+1][ar0]=b0.y; Bs[ac0+2][ar0]=b0.z; Bs[ac0+3][ar0]=b0.w;
    Bs[ac1+0][ar1]=b1.x; Bs[ac1+1][ar1]=b1.y; Bs[ac1+2][ar1]=b1.z; Bs[ac1+3][ar1]=b1.w;

    const int NT = KDIM / 16;  // 84
    for (int kt = 0; kt < NT; ++kt) {
        __syncthreads();
        if (kt + 1 < NT) {
            const int off = (kt + 1) * 16;
            a0 = *(const float4*)(aptr0 + off);
            a1 = *(const float4*)(aptr1 + off);
            b0 = v0 ? *(const float4*)(bptr0 + off) : z4;
            b1 = v1 ? *(const float4*)(bptr1 + off) : z4;
        }
#pragma unroll
        for (int kk = 0; kk < 16; ++kk) {
            float4 Av0 = *(const float4*)&As[kk][ty * 8];
            float4 Av1 = *(const float4*)&As[kk][ty * 8 + 4];
            float4 Bv0 = *(const float4*)&Bs[kk][tx * 8];
            float4 Bv1 = *(const float4*)&Bs[kk][tx * 8 + 4];
            ull bp0 = pack2(Bv0.x, Bv0.y), bp1 = pack2(Bv0.z, Bv0.w);
            ull bp2 = pack2(Bv1.x, Bv1.y), bp3 = pack2(Bv1.z, Bv1.w);
            float av[8] = {Av0.x, Av0.y, Av0.z, Av0.w, Av1.x, Av1.y, Av1.z, Av1.w};
#pragma unroll
            for (int i = 0; i < 8; i++) {
                ull ap = pack2(av[i], av[i]);
                fma2(acc[i][0], ap, bp0);
                fma2(acc[i][1], ap, bp1);
                fma2(acc[i][2], ap, bp2);
                fma2(acc[i][3], ap, bp3);
            }
        }
        __syncthreads();
        if (kt + 1 < NT) {
            As[ac0+0][ar0]=a0.x; As[ac0+1][ar0]=a0.y; As[ac0+2][ar0]=a0.z; As[ac0+3][ar0]=a0.w;
            As[ac1+0][ar1]=a1.x; As[ac1+1][ar1]=a1.y; As[ac1+2][ar1]=a1.z; As[ac1+3][ar1]=a1.w;
            Bs[ac0+0][ar0]=b0.x; Bs[ac0+1][ar0]=b0.y; Bs[ac0+2][ar0]=b0.z; Bs[ac0+3][ar0]=b0.w;
            Bs[ac1+0][ar1]=b1.x; Bs[ac1+1][ar1]=b1.y; Bs[ac1+2][ar1]=b1.z; Bs[ac1+3][ar1]=b1.w;
        }
    }

    // epilogue: bias + relu + store
    const int m0 = ty * 8, nn0 = n0 + tx * 8;
    float bvs[8];
#pragma unroll
    for (int j = 0; j < 8; j++) bvs[j] = (nn0 + j < ODIM) ? bias[nn0 + j] : 0.f;

#pragma unroll
    for (int i = 0; i < 8; i++) {
        float vcol[8];
#pragma unroll
        for (int j4 = 0; j4 < 4; j4++) unpack2(acc[i][j4], vcol[j4 * 2], vcol[j4 * 2 + 1]);
#pragma unroll
        for (int j = 0; j < 8; j++) vcol[j] = fmaxf(vcol[j] + bvs[j], 0.f);
        float* crow = g_c + (m0 + i) * ODIM + nn0;
        if (nn0 + 7 < ODIM) {
            *(float4*)(crow)     = make_float4(vcol[0], vcol[1], vcol[2], vcol[3]);
            *(float4*)(crow + 4) = make_float4(vcol[4], vcol[5], vcol[6], vcol[7]);
        } else {
#pragma unroll
            for (int j = 0; j < 8; j++) if (nn0 + j < ODIM) crow[j] = vcol[j];
        }
    }
}

// ============================================================
// Kernel 2: diagonal sum  res1T[t][b][h] = sum_k c[b][h,k,k+t]
// ============================================================
__global__ void res1_kernel()
{
    const int bh = blockIdx.x;          // 0..6399
    const int b = bh / HIDC, h = bh % HIDC;
    const int t = threadIdx.x;
    if (t >= Ll) return;
    const float* base = g_c + b * ODIM + h * (CKc * Pp);
    float v = 0.f;
#pragma unroll
    for (int k = 0; k < CKc; k++) v += base[k * (Pp + 1) + t];
    g_res1T[t * (Bb * HIDC) + b * HIDC + h] = v;
}

// ============================================================
// Kernel 3: GRU1 (hid=50, 163 steps). One CTA per batch row.
//   Per-thread weight rows in registers; h/x broadcast from smem.
// ============================================================
__global__ __launch_bounds__(160) void gru1_kernel(
    const float* __restrict__ wih, const float* __restrict__ whh,
    const float* __restrict__ bih, const float* __restrict__ bhh)
{
    __shared__ float sx[HIDC], sh[HIDR], sgi[150], sgh[150];
    const int b = blockIdx.x, tid = threadIdx.x;

    float wi[50], wh[50], bi = 0.f, bh_ = 0.f;
    if (tid < 150) {
        bi = bih[tid]; bh_ = bhh[tid];
#pragma unroll
        for (int i = 0; i < 50; i++) { wi[i] = wih[tid * 50 + i]; wh[i] = whh[tid * 50 + i]; }
    }
    if (tid < 50) sh[tid] = 0.f;
    __syncthreads();

    for (int t = 0; t < Ll; t++) {
        if (tid < 50) sx[tid] = g_res1T[t * (Bb * HIDC) + b * HIDC + tid];
        __syncthreads();
        if (tid < 150) {
            float gi = bi, gh = bh_;
#pragma unroll
            for (int i = 0; i < 50; i++) { gi += wi[i] * sx[i]; gh += wh[i] * sh[i]; }
            sgi[tid] = gi; sgh[tid] = gh;
        }
        __syncthreads();
        if (tid < 50) {
            float rr = sigm(sgi[tid] + sgh[tid]);
            float zz = sigm(sgi[tid + 50] + sgh[tid + 50]);
            float nn = tanh_fast(sgi[tid + 100] + rr * sgh[tid + 100]);
            sh[tid] = (1.f - zz) * nn + zz * sh[tid];
        }
    }
    __syncthreads();
    if (tid < 50) g_h1[b * HIDR + tid] = sh[tid];
}

// ============================================================
// Kernel 4: skip GRU (hid=5, 6 steps, 3072 independent rows; 1 thread/row)
// ============================================================
__global__ __launch_bounds__(128) void grus_kernel(
    const float* __restrict__ wih, const float* __restrict__ whh,
    const float* __restrict__ bih, const float* __restrict__ bhh)
{
    __shared__ float swi[15][50], swh[15][5], sbi[15], sbh[15];
    const int tid = threadIdx.x;
    for (int i = tid; i < 750; i += 128) swi[i / 50][i % 50] = wih[i];
    if (tid < 75) swh[tid / 5][tid % 5] = whh[tid];
    if (tid < 15) { sbi[tid] = bih[tid]; sbh[tid] = bhh[tid]; }
    __syncthreads();

    const int n = blockIdx.x * 128 + tid;    // 0..3071
    const int b = n / SKIP, jj = n % SKIP;
    float h[5] = {0.f, 0.f, 0.f, 0.f, 0.f};

    for (int pt = 0; pt < PTt; ++pt) {
        const int trow = (Ll - PTt * SKIP) + pt * SKIP + jj;   // 19 + 24*pt + jj
        const float* xr = g_res1T + trow * (Bb * HIDC) + b * HIDC;
        float g[15];
#pragma unroll
        for (int j = 0; j < 15; j++) g[j] = sbi[j];
        for (int i = 0; i < 50; i++) {
            float xv = xr[i];
#pragma unroll
            for (int j = 0; j < 15; j++) g[j] += xv * swi[j][i];
        }
        float gh[15];
#pragma unroll
        for (int j = 0; j < 15; j++) {
            float a = sbh[j];
#pragma unroll
            for (int u = 0; u < 5; u++) a += swh[j][u] * h[u];
            gh[j] = a;
        }
#pragma unroll
        for (int u = 0; u < 5; u++) {
            float rr = sigm(g[u] + gh[u]);
            float zz = sigm(g[5 + u] + gh[5 + u]);
            float nn = tanh_fast(g[10 + u] + rr * gh[10 + u]);
            h[u] = (1.f - zz) * nn + zz * h[u];
        }
    }
#pragma unroll
    for (int u = 0; u < 5; u++) g_hs[n * 5 + u] = h[u];
}

// ============================================================
// Kernel 5: final linear + highway + sigmoid
// ============================================================
__global__ void final_kernel(
    const float* __restrict__ x,
    const float* __restrict__ l1w, const float* __restrict__ l1b,
    const float* __restrict__ hww, const float* __restrict__ hwb,
    float* __restrict__ out)
{
    const int idx = blockIdx.x * blockDim.x + threadIdx.x;
    if (idx >= Bb * Mtot) return;
    const int b = idx / Mtot, m = idx % Mtot;

    float acc = l1b[m] + hwb[0];
    const float* wrow = l1w + m * (HIDR + SKIP * HIDS);
    const float* h1r = g_h1 + b * HIDR;
#pragma unroll
    for (int i = 0; i < HIDR; i++) acc += h1r[i] * wrow[i];
    const float* hsr = g_hs + b * (SKIP * HIDS);
#pragma unroll
    for (int i = 0; i < SKIP * HIDS; i++) acc += hsr[i] * wrow[HIDR + i];
    const float* xr = x + b * KDIM + (Pp - HWw) * Mtot + m;
#pragma unroll
    for (int wq = 0; wq < HWw; wq++) acc += xr[wq * Mtot] * hww[wq];

    out[idx] = sigm(acc);
}

// ============================================================
extern "C" void kernel_launch(void* const* d_in, const int* in_sizes, int n_in,
                              void* d_out, int out_size)
{
    const float* x     = (const float*)d_in[0];
    const float* convw = (const float*)d_in[1];
    const float* convb = (const float*)d_in[2];
    const float* g1wih = (const float*)d_in[3];
    const float* g1whh = (const float*)d_in[4];
    const float* g1bih = (const float*)d_in[5];
    const float* g1bhh = (const float*)d_in[6];
    const float* gswih = (const float*)d_in[7];
    const float* gswhh = (const float*)d_in[8];
    const float* gsbih = (const float*)d_in[9];
    const float* gsbhh = (const float*)d_in[10];
    const float* l1w   = (const float*)d_in[11];
    const float* l1b   = (const float*)d_in[12];
    const float* hww   = (const float*)d_in[13];
    const float* hwb   = (const float*)d_in[14];
    float* out = (float*)d_out;

    conv_gemm_kernel<<<(ODIM + 127) / 128, 256>>>(x, convw, convb);
    res1_kernel<<<Bb * HIDC, 192>>>();
    gru1_kernel<<<Bb, 160>>>(g1wih, g1whh, g1bih, g1bhh);
    grus_kernel<<<(Bb * SKIP) / 128, 128>>>(gswih, gswhh, gsbih, gsbhh);
    final_kernel<<<4, 256>>>(x, l1w, l1b, hww, hwb, out);
}

// round 3
// speedup vs baseline: 1.9963x; 1.9963x over previous
#include <cuda_runtime.h>
#include <cstdint>
#include <math.h>

#define Bb   128
#define Pp   168
#define Mtot 8
#define HIDC 50
#define HIDR 50
#define HIDS 5
#define CKc  6
#define SKIP 24
#define HWw  24
#define PTt  6            // (P-CK)/SKIP
#define Ll   163          // P-CK+1
#define KDIM 1344         // P*M1*M2*M3
#define ODIM 50400        // P*HIDC*CK

// ---- scratch (device globals; no allocation allowed) ----
__device__ float g_c[Bb * ODIM];                    // conv output [b][o] (25.8 MB)
__device__ float g_res1T[Ll * Bb * HIDC];           // [t][b][h]   for gru1
__device__ float g_resS[PTt * HIDC * (Bb * SKIP)];  // [pt][h][n]  for skip gru
__device__ float g_h1[Bb * HIDR];
__device__ float g_hs[Bb * SKIP * HIDS];            // [n][u], n = b*24+jj

__device__ __forceinline__ float sigm(float v) { return 1.f / (1.f + __expf(-v)); }
__device__ __forceinline__ float tanh_fast(float v) { return 2.f / (1.f + __expf(-2.f * v)) - 1.f; }

__device__ __forceinline__ float tf32_rnd(float v) {
    uint32_t u;
    asm("cvt.rna.tf32.f32 %0, %1;" : "=r"(u) : "f"(v));
    return __uint_as_float(u);
}

__device__ __forceinline__ void mma_tf32(float* c,
    uint32_t a0, uint32_t a1, uint32_t a2, uint32_t a3,
    uint32_t b0, uint32_t b1)
{
    asm volatile(
        "mma.sync.aligned.m16n8k8.row.col.f32.tf32.tf32.f32 "
        "{%0,%1,%2,%3}, {%4,%5,%6,%7}, {%8,%9}, {%0,%1,%2,%3};"
        : "+f"(c[0]), "+f"(c[1]), "+f"(c[2]), "+f"(c[3])
        : "r"(a0), "r"(a1), "r"(a2), "r"(a3), "r"(b0), "r"(b1));
}

// ============================================================
// Kernel 1: conv GEMM via mma.sync tf32, 3xTF32 split (fp32-class accuracy)
//   C[b][o] = relu(x[b]·w[o] + bias[o])
//   Block tile 128(M=batch) x 128(N=out rows of w), K=1344, KC=16, 2 stages.
//   8 warps; warp tile 32x64 (2 x m16, 8 x n8).
// ============================================================
#define KC       16
#define NCHUNK   (KDIM / KC)      // 84
#define PITCH    20               // floats per row (conflict-free for frag loads)
#define T_FLOATS (128 * PITCH)    // 2560 floats per tensor
#define OFF_AHI  0
#define OFF_ALO  (T_FLOATS)
#define OFF_BHI  (2 * T_FLOATS)
#define OFF_BLO  (3 * T_FLOATS)
#define STG_FLOATS (4 * T_FLOATS) // 10240 floats per stage
#define CONV_DSMEM (2 * STG_FLOATS * 4)  // 81920 bytes

__global__ __launch_bounds__(256, 1) void conv_mma_kernel(
    const float* __restrict__ x, const float* __restrict__ w,
    const float* __restrict__ bias)
{
    extern __shared__ float smem[];
    __shared__ float sbias[128];

    const int tid  = threadIdx.x;
    const int lane = tid & 31;
    const int wid  = tid >> 5;
    const int n0   = blockIdx.x * 128;

    const int warp_m = wid & 3;          // 0..3
    const int warp_n = wid >> 2;         // 0..1
    const int m_base = warp_m * 32;
    const int n_base = warp_n * 64;

    if (tid < 128) {
        const int col = n0 + tid;
        sbias[tid] = (col < ODIM) ? bias[col] : 0.f;
    }

    // gmem load mapping: 512 float4 slots per tensor; thread handles slots tid, tid+256
    const int r0 = tid >> 2, kq0 = (tid & 3) * 4;          // slot tid
    const int r1 = r0 + 64,  kq1 = kq0;                    // slot tid+256
    int wr0 = n0 + r0; if (wr0 >= ODIM) wr0 = ODIM - 1;
    int wr1 = n0 + r1; if (wr1 >= ODIM) wr1 = ODIM - 1;
    const float* xp0 = x + (size_t)r0 * KDIM + kq0;
    const float* xp1 = x + (size_t)r1 * KDIM + kq1;
    const float* wp0 = w + (size_t)wr0 * KDIM + kq0;
    const float* wp1 = w + (size_t)wr1 * KDIM + kq1;

    float acc[2][8][4];
#pragma unroll
    for (int mt = 0; mt < 2; mt++)
#pragma unroll
        for (int nt = 0; nt < 8; nt++)
#pragma unroll
            for (int j = 0; j < 4; j++) acc[mt][nt][j] = 0.f;

    // ---- stage chunk 0 ----
    {
        float4 a0 = *(const float4*)(xp0);
        float4 a1 = *(const float4*)(xp1);
        float4 b0 = *(const float4*)(wp0);
        float4 b1 = *(const float4*)(wp1);
        float* st = smem;   // stage 0
        const float av0[4] = {a0.x, a0.y, a0.z, a0.w};
        const float av1[4] = {a1.x, a1.y, a1.z, a1.w};
        const float bv0[4] = {b0.x, b0.y, b0.z, b0.w};
        const float bv1[4] = {b1.x, b1.y, b1.z, b1.w};
#pragma unroll
        for (int j = 0; j < 4; j++) {
            float h, l;
            h = tf32_rnd(av0[j]); l = tf32_rnd(av0[j] - h);
            st[OFF_AHI + r0 * PITCH + kq0 + j] = h; st[OFF_ALO + r0 * PITCH + kq0 + j] = l;
            h = tf32_rnd(av1[j]); l = tf32_rnd(av1[j] - h);
            st[OFF_AHI + r1 * PITCH + kq1 + j] = h; st[OFF_ALO + r1 * PITCH + kq1 + j] = l;
            h = tf32_rnd(bv0[j]); l = tf32_rnd(bv0[j] - h);
            st[OFF_BHI + r0 * PITCH + kq0 + j] = h; st[OFF_BLO + r0 * PITCH + kq0 + j] = l;
            h = tf32_rnd(bv1[j]); l = tf32_rnd(bv1[j] - h);
            st[OFF_BHI + r1 * PITCH + kq1 + j] = h; st[OFF_BLO + r1 * PITCH + kq1 + j] = l;
        }
    }

    for (int i = 0; i < NCHUNK; i++) {
        __syncthreads();

        // prefetch next chunk into registers
        float4 pa0, pa1, pb0, pb1;
        const bool more = (i + 1 < NCHUNK);
        if (more) {
            const int kb = (i + 1) * KC;
            pa0 = *(const float4*)(xp0 + kb);
            pa1 = *(const float4*)(xp1 + kb);
            pb0 = *(const float4*)(wp0 + kb);
            pb1 = *(const float4*)(wp1 + kb);
        }

        // compute on stage i&1
        const float* st = smem + (i & 1) * STG_FLOATS;
        const uint32_t* Ahi = (const uint32_t*)(st + OFF_AHI);
        const uint32_t* Alo = (const uint32_t*)(st + OFF_ALO);
        const uint32_t* Bhi = (const uint32_t*)(st + OFF_BHI);
        const uint32_t* Blo = (const uint32_t*)(st + OFF_BLO);

#pragma unroll
        for (int ks = 0; ks < 2; ks++) {
            const int k0 = ks * 8 + (lane & 3);
            uint32_t ah[2][4], al[2][4];
#pragma unroll
            for (int mt = 0; mt < 2; mt++) {
                const int m0 = m_base + mt * 16 + (lane >> 2);
                ah[mt][0] = Ahi[m0 * PITCH + k0];
                ah[mt][1] = Ahi[(m0 + 8) * PITCH + k0];
                ah[mt][2] = Ahi[m0 * PITCH + k0 + 4];
                ah[mt][3] = Ahi[(m0 + 8) * PITCH + k0 + 4];
                al[mt][0] = Alo[m0 * PITCH + k0];
                al[mt][1] = Alo[(m0 + 8) * PITCH + k0];
                al[mt][2] = Alo[m0 * PITCH + k0 + 4];
                al[mt][3] = Alo[(m0 + 8) * PITCH + k0 + 4];
            }
#pragma unroll
            for (int nt = 0; nt < 8; nt++) {
                const int nn = n_base + nt * 8 + (lane >> 2);
                const uint32_t bh0 = Bhi[nn * PITCH + k0];
                const uint32_t bh1 = Bhi[nn * PITCH + k0 + 4];
                const uint32_t bl0 = Blo[nn * PITCH + k0];
                const uint32_t bl1 = Blo[nn * PITCH + k0 + 4];
#pragma unroll
                for (int mt = 0; mt < 2; mt++) {
                    mma_tf32(acc[mt][nt], ah[mt][0], ah[mt][1], ah[mt][2], ah[mt][3], bh0, bh1);
                    mma_tf32(acc[mt][nt], ah[mt][0], ah[mt][1], ah[mt][2], ah[mt][3], bl0, bl1);
                    mma_tf32(acc[mt][nt], al[mt][0], al[mt][1], al[mt][2], al[mt][3], bh0, bh1);
                }
            }
        }

        // store prefetched chunk to the other stage
        if (more) {
            float* st2 = smem + ((i + 1) & 1) * STG_FLOATS;
            const float av0[4] = {pa0.x, pa0.y, pa0.z, pa0.w};
            const float av1[4] = {pa1.x, pa1.y, pa1.z, pa1.w};
            const float bv0[4] = {pb0.x, pb0.y, pb0.z, pb0.w};
            const float bv1[4] = {pb1.x, pb1.y, pb1.z, pb1.w};
#pragma unroll
            for (int j = 0; j < 4; j++) {
                float h, l;
                h = tf32_rnd(av0[j]); l = tf32_rnd(av0[j] - h);
                st2[OFF_AHI + r0 * PITCH + kq0 + j] = h; st2[OFF_ALO + r0 * PITCH + kq0 + j] = l;
                h = tf32_rnd(av1[j]); l = tf32_rnd(av1[j] - h);
                st2[OFF_AHI + r1 * PITCH + kq1 + j] = h; st2[OFF_ALO + r1 * PITCH + kq1 + j] = l;
                h = tf32_rnd(bv0[j]); l = tf32_rnd(bv0[j] - h);
                st2[OFF_BHI + r0 * PITCH + kq0 + j] = h; st2[OFF_BLO + r0 * PITCH + kq0 + j] = l;
                h = tf32_rnd(bv1[j]); l = tf32_rnd(bv1[j] - h);
                st2[OFF_BHI + r1 * PITCH + kq1 + j] = h; st2[OFF_BLO + r1 * PITCH + kq1 + j] = l;
            }
        }
    }

    // ---- epilogue: bias + relu, store straight from registers ----
#pragma unroll
    for (int mt = 0; mt < 2; mt++) {
        const int rA = m_base + mt * 16 + (lane >> 2);
#pragma unroll
        for (int nt = 0; nt < 8; nt++) {
            const int cl = n_base + nt * 8 + (lane & 3) * 2;   // local col (even)
            const int cg = n0 + cl;
            if (cg < ODIM) {
                const float b0v = sbias[cl], b1v = sbias[cl + 1];
                float2 v0, v1;
                v0.x = fmaxf(acc[mt][nt][0] + b0v, 0.f);
                v0.y = fmaxf(acc[mt][nt][1] + b1v, 0.f);
                v1.x = fmaxf(acc[mt][nt][2] + b0v, 0.f);
                v1.y = fmaxf(acc[mt][nt][3] + b1v, 0.f);
                *(float2*)(g_c + (size_t)rA * ODIM + cg) = v0;
                *(float2*)(g_c + (size_t)(rA + 8) * ODIM + cg) = v1;
            }
        }
    }
}

// ============================================================
// Kernel 2: diagonal sum -> both layouts
// ============================================================
__global__ void res1_kernel()
{
    const int bh = blockIdx.x;          // 0..6399
    const int b = bh / HIDC, h = bh % HIDC;
    const int t = threadIdx.x;
    if (t >= Ll) return;
    const float* basep = g_c + (size_t)b * ODIM + h * (CKc * Pp);
    float v = 0.f;
#pragma unroll
    for (int k = 0; k < CKc; k++) v += basep[k * (Pp + 1) + t];
    g_res1T[t * (Bb * HIDC) + b * HIDC + h] = v;
    const int tr = t - (Ll - PTt * SKIP);   // t - 19
    if (tr >= 0) {
        const int pt = tr / SKIP, jj = tr % SKIP;
        g_resS[(pt * HIDC + h) * (Bb * SKIP) + b * SKIP + jj] = v;
    }
}

// ============================================================
// Kernel 3: GRU1 (hid=50, 163 steps). One CTA per batch row.
// ============================================================
__global__ __launch_bounds__(160) void gru1_kernel(
    const float* __restrict__ wih, const float* __restrict__ whh,
    const float* __restrict__ bih, const float* __restrict__ bhh)
{
    __shared__ float sx[HIDC], sh[HIDR], sgi[150], sgh[150];
    const int b = blockIdx.x, tid = threadIdx.x;

    float wi[50], wh[50], bi = 0.f, bh_ = 0.f;
    if (tid < 150) {
        bi = bih[tid]; bh_ = bhh[tid];
#pragma unroll
        for (int i = 0; i < 50; i++) { wi[i] = wih[tid * 50 + i]; wh[i] = whh[tid * 50 + i]; }
    }
    if (tid < 50) sh[tid] = 0.f;
    __syncthreads();

    for (int t = 0; t < Ll; t++) {
        if (tid < 50) sx[tid] = g_res1T[t * (Bb * HIDC) + b * HIDC + tid];
        __syncthreads();
        if (tid < 150) {
            float gi = bi, gh = bh_;
#pragma unroll
            for (int i = 0; i < 50; i++) { gi += wi[i] * sx[i]; gh += wh[i] * sh[i]; }
            sgi[tid] = gi; sgh[tid] = gh;
        }
        __syncthreads();
        if (tid < 50) {
            float rr = sigm(sgi[tid] + sgh[tid]);
            float zz = sigm(sgi[tid + 50] + sgh[tid + 50]);
            float nn = tanh_fast(sgi[tid + 100] + rr * sgh[tid + 100]);
            sh[tid] = (1.f - zz) * nn + zz * sh[tid];
        }
    }
    __syncthreads();
    if (tid < 50) g_h1[b * HIDR + tid] = sh[tid];
}

// ============================================================
// Kernel 4: skip GRU — 5 threads per row (one per hidden unit), coalesced x
// ============================================================
__global__ __launch_bounds__(160) void grus_kernel(
    const float* __restrict__ wih, const float* __restrict__ whh,
    const float* __restrict__ bih, const float* __restrict__ bhh)
{
    __shared__ float swi[15][50], swh[15][5], sbi[15], sbh[15];
    __shared__ float sx[50][32];
    __shared__ float sh[5][32];
    const int tid = threadIdx.x;
    for (int i = tid; i < 750; i += 160) swi[i / 50][i % 50] = wih[i];
    if (tid < 75) swh[tid / 5][tid % 5] = whh[tid];
    if (tid < 15) { sbi[tid] = bih[tid]; sbh[tid] = bhh[tid]; }

    const int u = tid >> 5, rl = tid & 31;
    const int n0 = blockIdx.x * 32;
    sh[u][rl] = 0.f;
    float h = 0.f;

    for (int pt = 0; pt < PTt; ++pt) {
        __syncthreads();
        for (int q = tid; q < 1600; q += 160) {
            const int i = q >> 5, r = q & 31;
            sx[i][r] = g_resS[(pt * HIDC + i) * (Bb * SKIP) + n0 + r];
        }
        float gh0 = sbh[u], gh1 = sbh[5 + u], gh2 = sbh[10 + u];
#pragma unroll
        for (int u2 = 0; u2 < 5; u2++) {
            const float hv = sh[u2][rl];
            gh0 += swh[u][u2] * hv;
            gh1 += swh[5 + u][u2] * hv;
            gh2 += swh[10 + u][u2] * hv;
        }
        __syncthreads();
        float g0 = sbi[u], g1 = sbi[5 + u], g2 = sbi[10 + u];
#pragma unroll
        for (int i = 0; i < 50; i++) {
            const float xv = sx[i][rl];
            g0 += xv * swi[u][i];
            g1 += xv * swi[5 + u][i];
            g2 += xv * swi[10 + u][i];
        }
        const float rr = sigm(g0 + gh0);
        const float zz = sigm(g1 + gh1);
        const float nn = tanh_fast(g2 + rr * gh2);
        h = (1.f - zz) * nn + zz * h;
        sh[u][rl] = h;
    }
    g_hs[(n0 + rl) * HIDS + u] = h;
}

// ============================================================
// Kernel 5: final linear + highway + sigmoid
// ============================================================
__global__ void final_kernel(
    const float* __restrict__ x,
    const float* __restrict__ l1w, const float* __restrict__ l1b,
    const float* __restrict__ hww, const float* __restrict__ hwb,
    float* __restrict__ out)
{
    const int idx = blockIdx.x * blockDim.x + threadIdx.x;
    if (idx >= Bb * Mtot) return;
    const int b = idx / Mtot, m = idx % Mtot;

    float acc = l1b[m] + hwb[0];
    const float* wrow = l1w + m * (HIDR + SKIP * HIDS);
    const float* h1r = g_h1 + b * HIDR;
#pragma unroll
    for (int i = 0; i < HIDR; i++) acc += h1r[i] * wrow[i];
    const float* hsr = g_hs + b * (SKIP * HIDS);
#pragma unroll
    for (int i = 0; i < SKIP * HIDS; i++) acc += hsr[i] * wrow[HIDR + i];
    const float* xr = x + b * KDIM + (Pp - HWw) * Mtot + m;
#pragma unroll
    for (int wq = 0; wq < HWw; wq++) acc += xr[wq * Mtot] * hww[wq];

    out[idx] = sigm(acc);
}

// ============================================================
extern "C" void kernel_launch(void* const* d_in, const int* in_sizes, int n_in,
                              void* d_out, int out_size)
{
    const float* x     = (const float*)d_in[0];
    const float* convw = (const float*)d_in[1];
    const float* convb = (const float*)d_in[2];
    const float* g1wih = (const float*)d_in[3];
    const float* g1whh = (const float*)d_in[4];
    const float* g1bih = (const float*)d_in[5];
    const float* g1bhh = (const float*)d_in[6];
    const float* gswih = (const float*)d_in[7];
    const float* gswhh = (const float*)d_in[8];
    const float* gsbih = (const float*)d_in[9];
    const float* gsbhh = (const float*)d_in[10];
    const float* l1w   = (const float*)d_in[11];
    const float* l1b   = (const float*)d_in[12];
    const float* hww   = (const float*)d_in[13];
    const float* hwb   = (const float*)d_in[14];
    float* out = (float*)d_out;

    cudaFuncSetAttribute(conv_mma_kernel,
                         cudaFuncAttributeMaxDynamicSharedMemorySize, CONV_DSMEM);

    conv_mma_kernel<<<(ODIM + 127) / 128, 256, CONV_DSMEM>>>(x, convw, convb);
    res1_kernel<<<Bb * HIDC, 192>>>();
    gru1_kernel<<<Bb, 160>>>(g1wih, g1whh, g1bih, g1bhh);
    grus_kernel<<<(Bb * SKIP) / 32, 160>>>(gswih, gswhh, gsbih, gsbhh);
    final_kernel<<<4, 256>>>(x, l1w, l1b, hww, hwb, out);
}